// round 13
// baseline (speedup 1.0000x reference)
#include <cuda_runtime.h>
#include <cstdint>

#define DM    1024
#define DFF   2048
#define NROWS 32768
#define MAXT  264
#define PADROWS (MAXT*128)

// ---------------- scratch ----------------
__device__ float g_Xp [(size_t)MAXT*128*DM];    // gathered x, tf32-rounded, FRAGMENT-PACKED
__device__ float g_ACT[(size_t)MAXT*128*DFF];   // GLU activations, FRAGMENT-PACKED
__device__ float g_W1p[(size_t)8*4096*DM];      // W1 packed B-frags (64h||64gate per 128-tile)
__device__ float g_W2p[(size_t)8*DM*DFF];       // W2 packed B-frags
__device__ int   g_perm[PADROWS];
__device__ int   g_cnt[8];
__device__ int   g_tb[9];
__device__ unsigned g_det;                      // 0 -> indices int64, else int32

// ---------------- helpers ----------------
__device__ __forceinline__ float rtf(float a){ asm("cvt.rna.tf32.f32 %0, %0;":"+f"(a)); return a; }
__device__ __forceinline__ uint32_t fu(float f){ return __float_as_uint(f); }
__device__ __forceinline__ uint32_t su32(const void* p){
  uint32_t a; asm("{ .reg .u64 t; cvta.to.shared.u64 t, %1; cvt.u32.u64 %0, t; }":"=r"(a):"l"(p)); return a;
}
__device__ __forceinline__ void cp16(uint32_t d, const void* s){
  asm volatile("cp.async.cg.shared.global [%0], [%1], 16;" :: "r"(d), "l"(s) : "memory");
}
#define CPCOMMIT() asm volatile("cp.async.commit_group;":::"memory")
#define CPWAIT(n)  asm volatile("cp.async.wait_group %0;"::"n"(n):"memory")

__device__ __forceinline__ void mma8(float* c, const uint32_t* a, uint32_t b0, uint32_t b1){
  asm volatile("mma.sync.aligned.m16n8k8.row.col.f32.tf32.tf32.f32 "
    "{%0,%1,%2,%3},{%4,%5,%6,%7},{%8,%9},{%0,%1,%2,%3};"
    : "+f"(c[0]),"+f"(c[1]),"+f"(c[2]),"+f"(c[3])
    : "r"(a[0]),"r"(a[1]),"r"(a[2]),"r"(a[3]),"r"(b0),"r"(b1));
}

// ---------------- wconv1: W1 pack (64h||64gate per 128-N tile) + perm/cnt-init + detect ----
__global__ void k_wconv1(const float* __restrict__ W1, const unsigned* __restrict__ iw){
  if (blockIdx.x < 264) g_perm[blockIdx.x*128 + threadIdx.x] = -1;
  if (blockIdx.x == 264 && threadIdx.x < 8) g_cnt[threadIdx.x] = 0;
  if (blockIdx.x == 265){
    __shared__ unsigned red[4];
    unsigned v=0;
    for (int i=threadIdx.x; i<16384; i+=128) v |= iw[2*i+1];
    #pragma unroll
    for (int o=16;o>0;o>>=1) v |= __shfl_xor_sync(0xFFFFFFFFu, v, o);
    if ((threadIdx.x&31)==0) red[threadIdx.x>>5]=v;
    __syncthreads();
    if (threadIdx.x==0) g_det = red[0]|red[1]|red[2]|red[3];
  }
  __shared__ float sw[128][16];
  int b=blockIdx.x; int kc=b&63, nb=(b>>6)&31, e=b>>11;
  int r=threadIdx.x;                     // 0..127: 64 h rows then 64 gate rows
  int srow = (r<64)? (nb*64+r) : (2048 + nb*64 + (r-64));
  const float4* src = (const float4*)(W1 + ((size_t)e*4096 + srow)*DM + kc*16);
  #pragma unroll
  for (int q4=0;q4<4;q4++){
    float4 v=src[q4];
    sw[r][q4*4+0]=rtf(v.x); sw[r][q4*4+1]=rtf(v.y); sw[r][q4*4+2]=rtf(v.z); sw[r][q4*4+3]=rtf(v.w);
  }
  __syncthreads();
  float* dst = g_W1p + ((size_t)((e*32+nb)*64 + kc))*2048;
  #pragma unroll
  for (int u=0;u<4;u++){
    int q=r*4+u;                         // 0..511
    int cb=q>>8, s=(q>>7)&1, qq=(q>>5)&3, l=q&31;
    int n0=cb*64+qq*16+(l>>2), k0=s*8+(l&3);
    float4 v;
    v.x=sw[n0][k0];   v.y=sw[n0][k0+4];
    v.z=sw[n0+8][k0]; v.w=sw[n0+8][k0+4];
    *(float4*)(dst+q*4)=v;
  }
}
__global__ void k_wconv2(const float* __restrict__ W2){
  __shared__ float sw[128][16];
  int b=blockIdx.x; int kc=b&127, nb=(b>>7)&7, e=b>>10;
  int r=threadIdx.x;
  int srow = nb*128 + r;
  const float4* src = (const float4*)(W2 + ((size_t)e*1024 + srow)*DFF + kc*16);
  #pragma unroll
  for (int q4=0;q4<4;q4++){
    float4 v=src[q4];
    sw[r][q4*4+0]=rtf(v.x); sw[r][q4*4+1]=rtf(v.y); sw[r][q4*4+2]=rtf(v.z); sw[r][q4*4+3]=rtf(v.w);
  }
  __syncthreads();
  float* dst = g_W2p + ((size_t)((e*8+nb)*128 + kc))*2048;
  #pragma unroll
  for (int u=0;u<4;u++){
    int q=r*4+u;
    int cb=q>>8, s=(q>>7)&1, qq=(q>>5)&3, l=q&31;
    int n0=cb*64+qq*16+(l>>2), k0=s*8+(l&3);
    float4 v;
    v.x=sw[n0][k0];   v.y=sw[n0][k0+4];
    v.z=sw[n0+8][k0]; v.w=sw[n0+8][k0+4];
    *(float4*)(dst+q*4)=v;
  }
}

// ---------------- perm ----------------
__global__ void k_perm(const void* __restrict__ ind, const int* __restrict__ counts){
  int tb[9]; tb[0]=0;
  #pragma unroll
  for (int e=0;e<8;e++) tb[e+1] = tb[e] + ((counts[e]+127)>>7);
  if (blockIdx.x==0 && threadIdx.x<9) g_tb[threadIdx.x] = tb[threadIdx.x];
  int p = blockIdx.x*blockDim.x + threadIdx.x;
  if (p>=NROWS) return;
  int e;
  if (g_det==0u) e = (int)((const long long*)ind)[p];
  else           e = ((const int*)ind)[p];
  e &= 7;
  int s = (tb[e]<<7) + atomicAdd(&g_cnt[e],1);
  if (s >= PADROWS) s = PADROWS-1;
  g_perm[s] = p;
}

// ---------------- packA ----------------
__global__ void __launch_bounds__(256,1) k_packA(const float* __restrict__ x){
  __shared__ int sp[128];
  extern __shared__ float sm[];   // [128][132]
  int t = blockIdx.x>>3, kb8 = blockIdx.x&7;
  if (t>=g_tb[8]) return;
  int tid=threadIdx.x;
  if (tid<128) sp[tid]=g_perm[t*128+tid];
  __syncthreads();
  #pragma unroll
  for (int v=0;v<16;v++){
    int i=v*256+tid, row=i>>5, c4=i&31;
    int p=sp[row];
    float4 fv=make_float4(0.f,0.f,0.f,0.f);
    if (p>=0){
      fv = *(const float4*)(x + (size_t)(p>>1)*DM + kb8*128 + c4*4);
      fv.x=rtf(fv.x); fv.y=rtf(fv.y); fv.z=rtf(fv.z); fv.w=rtf(fv.w);
    }
    *(float4*)(sm + row*132 + c4*4) = fv;
  }
  __syncthreads();
  float* dst = g_Xp + (size_t)t*(128*DM);
  #pragma unroll
  for (int v=0;v<16;v++){
    int o=v*256+tid;
    int kcl=o>>9, s2=(o>>8)&1, g=(o>>5)&7, l=o&31, q=l>>2, kl=l&3;
    int row=16*g+q, col=kcl*16+s2*8+kl;
    float4 fv;
    fv.x=sm[row*132+col];     fv.y=sm[(row+8)*132+col];
    fv.z=sm[row*132+col+4];   fv.w=sm[(row+8)*132+col+4];
    int kb=kb8*8+kcl;
    *(float4*)(dst + ((size_t)kb*512 + s2*256 + g*32 + l)*4) = fv;
  }
}

// ---------------- GEMM: 128x128 CTA tile, 128 threads (2 m-warps x 2 n-warps, 64x64/warp),
// ---------------- K16 chunks, 4-stage, R7 pipeline invariants, 2 CTAs/SM ----------------
template<bool IS1>
__global__ void __launch_bounds__(128,2) k_gemm(float* __restrict__ out){
  constexpr int NKB = IS1 ? 64 : 128;
  extern __shared__ float sm[];
  int tid=threadIdx.x, lane=tid&31, wid=tid>>5;
  int mw=wid&1, nw=wid>>1;               // 2 m-warps x 2 n-warps (64x64 each)
  int t, nb;
  if (IS1){ t=blockIdx.x>>5; nb=blockIdx.x&31; }
  else    { t=blockIdx.x>>3; nb=blockIdx.x&7;  }
  if (t>=g_tb[8]) return;
  int e=0;
  #pragma unroll
  for (int q=1;q<8;q++) if (t>=g_tb[q]) e=q;

  const float* Ab = (IS1? g_Xp : g_ACT) + (size_t)t*(size_t)(128*(IS1?DM:DFF));
  const float* B0 = IS1 ? (g_W1p + (size_t)(e*32+nb)*(64*2048))
                        : (g_W2p + (size_t)(e*8+nb)*(128*2048));

  uint32_t sb = su32(sm);
  uint32_t Asb = sb, Bsb = sb + 32768;   // A: 4x2048 f32, B: 4x2048 f32

  float acc[4][8][4];
  #pragma unroll
  for (int i=0;i<4;i++)
    #pragma unroll
    for (int j=0;j<8;j++)
      #pragma unroll
      for (int c=0;c<4;c++) acc[i][j][c]=0.f;

  auto load = [&](int kb,int st){
    #pragma unroll
    for (int z=0;z<4;z++){
      cp16(Asb + st*8192 + (z*128+tid)*16, Ab + (size_t)kb*2048 + (z*128+tid)*4);
      cp16(Bsb + st*8192 + (z*128+tid)*16, B0 + (size_t)kb*2048 + (z*128+tid)*4);
    }
  };
  load(0,0); CPCOMMIT();
  load(1,1); CPCOMMIT();
  load(2,2); CPCOMMIT();

  for (int kb=0; kb<NKB; kb++){
    int st=kb&3;
    CPWAIT(2);
    __syncthreads();
    const float* A_s = sm + st*2048;
    const float* B_s = sm + 8192 + st*2048;
    #pragma unroll
    for (int s=0;s<2;s++){
      float4 af0 = *(const float4*)(A_s + s*1024 + (4*mw+0)*128 + lane*4);
      float4 af1 = *(const float4*)(A_s + s*1024 + (4*mw+1)*128 + lane*4);
      float4 af2 = *(const float4*)(A_s + s*1024 + (4*mw+2)*128 + lane*4);
      float4 af3 = *(const float4*)(A_s + s*1024 + (4*mw+3)*128 + lane*4);
      const float* bp = B_s + nw*1024 + s*512 + lane*4;
      float4 q0=*(const float4*)bp,       q1=*(const float4*)(bp+128),
             q2=*(const float4*)(bp+256), q3=*(const float4*)(bp+384);
      if (s==0){                                   // exactly ONE commit per kb iteration
        if (kb+3<NKB) load(kb+3,(kb+3)&3);
        CPCOMMIT();
      }
      uint32_t a0[4]={fu(af0.x),fu(af0.y),fu(af0.z),fu(af0.w)};
      uint32_t a1[4]={fu(af1.x),fu(af1.y),fu(af1.z),fu(af1.w)};
      uint32_t a2[4]={fu(af2.x),fu(af2.y),fu(af2.z),fu(af2.w)};
      uint32_t a3[4]={fu(af3.x),fu(af3.y),fu(af3.z),fu(af3.w)};
      float qv[16]={q0.x,q0.y,q0.z,q0.w, q1.x,q1.y,q1.z,q1.w,
                    q2.x,q2.y,q2.z,q2.w, q3.x,q3.y,q3.z,q3.w};
      #pragma unroll
      for (int j=0;j<8;j++){
        uint32_t b0=fu(qv[(j>>1)*4+(j&1)*2]), b1=fu(qv[(j>>1)*4+(j&1)*2+1]);
        mma8(acc[0][j],a0,b0,b1);
        mma8(acc[1][j],a1,b0,b1);
        mma8(acc[2][j],a2,b0,b1);
        mma8(acc[3][j],a3,b0,b1);
      }
    }
  }
  CPWAIT(0);
  __syncthreads();

  if (IS1){
    // GLU: warp cols nw*64 (nw=0 -> h, nw=1 -> gate); pair h[c] with gate[c] (same local col)
    // process 64-row halves sequentially: half w handled by warps with mw==w
    float* G  = sm;                      // [64][68] gate staging
    float* Gt = sm + 64*68;              // [64][68] activation staging
    float* actb = g_ACT + (size_t)t*(128*DFF);
    #pragma unroll
    for (int w=0;w<2;w++){
      if (mw==w && nw==1){               // gate warp of this half -> G
        #pragma unroll
        for (int mf=0;mf<4;mf++){
          int sr=mf*16+(lane>>2);
          #pragma unroll
          for (int j=0;j<8;j++){
            int col=j*8+(lane&3)*2;
            G[sr*68+col]    =acc[mf][j][0]; G[sr*68+col+1]    =acc[mf][j][1];
            G[(sr+8)*68+col]=acc[mf][j][2]; G[(sr+8)*68+col+1]=acc[mf][j][3];
          }
        }
      }
      __syncthreads();
      if (mw==w && nw==0){               // h warp: act = h*silu(gate) -> Gt
        #pragma unroll
        for (int mf=0;mf<4;mf++){
          int sr=mf*16+(lane>>2);
          #pragma unroll
          for (int j=0;j<8;j++){
            int col=j*8+(lane&3)*2;
            float g0=G[sr*68+col],     g1=G[sr*68+col+1];
            float g2=G[(sr+8)*68+col], g3=G[(sr+8)*68+col+1];
            Gt[sr*68+col]      = rtf(acc[mf][j][0]*g0*(1.f/(1.f+__expf(-g0))));
            Gt[sr*68+col+1]    = rtf(acc[mf][j][1]*g1*(1.f/(1.f+__expf(-g1))));
            Gt[(sr+8)*68+col]  = rtf(acc[mf][j][2]*g2*(1.f/(1.f+__expf(-g2))));
            Gt[(sr+8)*68+col+1]= rtf(acc[mf][j][3]*g3*(1.f/(1.f+__expf(-g3))));
          }
        }
      }
      __syncthreads();
      // packed ACT write for this 64-row half: 1024 float4, 128 threads -> 8 each
      #pragma unroll
      for (int v=0;v<8;v++){
        int o=v*128+tid;
        int kcl=o>>8, s2=(o>>7)&1, g=(o>>5)&3, l=o&31, q=l>>2, kl=l&3;
        int row=g*16+q, col=kcl*16+s2*8+kl;   // row 0..63 (half-local), col 0..63
        float4 fv;
        fv.x=Gt[row*68+col];     fv.y=Gt[(row+8)*68+col];
        fv.z=Gt[row*68+col+4];   fv.w=Gt[(row+8)*68+col+4];
        int kb=nb*4+kcl, gg=w*4+g;
        *(float4*)(actb + ((size_t)kb*512 + s2*256 + gg*32 + l)*4) = fv;
      }
      __syncthreads();
    }
  } else {
    // scatter epilogue
    #pragma unroll
    for (int mf=0;mf<4;mf++){
      int r=mw*64+mf*16+(lane>>2);
      int p0=g_perm[t*128+r], p1=g_perm[t*128+r+8];
      #pragma unroll
      for (int j=0;j<8;j++){
        int col=nb*128+nw*64+j*8+(lane&3)*2;
        if (p0>=0) *(float2*)(out+(size_t)p0*DM+col)=make_float2(acc[mf][j][0],acc[mf][j][1]);
        if (p1>=0) *(float2*)(out+(size_t)p1*DM+col)=make_float2(acc[mf][j][2],acc[mf][j][3]);
      }
    }
  }
}

// ---------------- host ----------------
extern "C" void kernel_launch(void* const* d_in, const int* in_sizes, int n_in,
                              void* d_out, int out_size){
  const float* x   = (const float*)d_in[0];
  const float* w1  = (const float*)d_in[1];
  const float* w2  = (const float*)d_in[2];
  const void*  ind = d_in[3];
  const int*   cnt = (const int*)d_in[4];
  float* out = (float*)d_out;
  (void)in_sizes; (void)n_in; (void)out_size;

  const int SMG = (4*2048 + 4*2048)*4;   // 65536 B per CTA (2 CTAs/SM)
  const int SMP = 128*132*4;             // 67584 B
  cudaFuncSetAttribute((const void*)k_gemm<true>,  cudaFuncAttributeMaxDynamicSharedMemorySize, SMG);
  cudaFuncSetAttribute((const void*)k_gemm<false>, cudaFuncAttributeMaxDynamicSharedMemorySize, SMG);
  cudaFuncSetAttribute((const void*)k_packA, cudaFuncAttributeMaxDynamicSharedMemorySize, SMP);

  k_wconv1<<<16384, 128>>>(w1, (const unsigned*)ind); // + perm/cnt init + dtype detect
  k_perm<<<128, 256>>>(ind, cnt);                     // + publishes g_tb
  k_packA<<<MAXT*8, 256, SMP>>>(x);
  k_gemm<true ><<<MAXT*32, 128, SMG>>>(nullptr);      // 4th launch -> ncu capture slot
  k_wconv2<<<8192, 128>>>(w2);
  k_gemm<false><<<MAXT*8,  128, SMG>>>(out);
}

// round 14
// speedup vs baseline: 1.9543x; 1.9543x over previous
#include <cuda_runtime.h>
#include <cuda_fp16.h>
#include <cstdint>

#define DM    1024
#define DFF   2048
#define NROWS 32768
#define MAXT  264
#define PADROWS (MAXT*128)

// ---------------- scratch (fp16 packed as uint32 half2) ----------------
__device__ unsigned g_Xp [(size_t)MAXT*65536];    // x packed: 32 chunks x 2048 u32 per tile
__device__ unsigned g_ACT[(size_t)MAXT*131072];   // ACT packed: 64 chunks x 2048 u32 per tile
__device__ unsigned g_W1p[(size_t)8*32*32*2048];  // W1: per (e,nb): 32 chunks x 2048 u32
__device__ unsigned g_W2p[(size_t)8*8*64*2048];   // W2: per (e,nb): 64 chunks x 2048 u32
__device__ int   g_perm[PADROWS];
__device__ int   g_cnt[8];
__device__ int   g_tb[9];
__device__ unsigned g_det;                        // 0 -> indices int64, else int32

// ---------------- helpers ----------------
__device__ __forceinline__ uint32_t h2(float a, float b){
  __half2 v = __floats2half2_rn(a, b);
  return *reinterpret_cast<uint32_t*>(&v);
}
__device__ __forceinline__ uint32_t su32(const void* p){
  uint32_t a; asm("{ .reg .u64 t; cvta.to.shared.u64 t, %1; cvt.u32.u64 %0, t; }":"=r"(a):"l"(p)); return a;
}
__device__ __forceinline__ void cp16(uint32_t d, const void* s){
  asm volatile("cp.async.cg.shared.global [%0], [%1], 16;" :: "r"(d), "l"(s) : "memory");
}
#define CPCOMMIT() asm volatile("cp.async.commit_group;":::"memory")
#define CPWAIT(n)  asm volatile("cp.async.wait_group %0;"::"n"(n):"memory")

__device__ __forceinline__ void mma16(float* c, const uint32_t* a, uint32_t b0, uint32_t b1){
  asm volatile("mma.sync.aligned.m16n8k16.row.col.f32.f16.f16.f32 "
    "{%0,%1,%2,%3},{%4,%5,%6,%7},{%8,%9},{%0,%1,%2,%3};"
    : "+f"(c[0]),"+f"(c[1]),"+f"(c[2]),"+f"(c[3])
    : "r"(a[0]),"r"(a[1]),"r"(a[2]),"r"(a[3]),"r"(b0),"r"(b1));
}

// B-pack for one 32-K chunk: u in [0,2048): u = nw*1024 + s*512 + qb*128 + l*4 + el
//   j = 2qb + (el>>1); n = nw*64 + j*8 + (l>>2); k = s*16 + 2*(l&3) + 8*(el&1)
//   value = half2( W[n][k], W[n][k+1] )
// A-pack: u = s*1024 + g*128 + l*4 + el
//   row = 16g + (l>>2) + 8*(el&1); k = s*16 + 2*(l&3) + 8*(el>>1)
//   value = half2( A[row][k], A[row][k+1] )

// ---------------- wconv1: W1 pack (64h||64gate per nb) + perm/cnt-init + detect ----------------
// grid 8192 = [e(3)][nb(5)][ch(6->5? ch in 0..31)] : b = e*1024 + nb*32 + ch
__global__ void k_wconv1(const float* __restrict__ W1, const unsigned* __restrict__ iw){
  if (blockIdx.x < 264) g_perm[blockIdx.x*128 + threadIdx.x] = -1;
  if (blockIdx.x == 264 && threadIdx.x < 8) g_cnt[threadIdx.x] = 0;
  if (blockIdx.x == 265){
    __shared__ unsigned red[4];
    unsigned v=0;
    for (int i=threadIdx.x; i<16384; i+=128) v |= iw[2*i+1];
    #pragma unroll
    for (int o=16;o>0;o>>=1) v |= __shfl_xor_sync(0xFFFFFFFFu, v, o);
    if ((threadIdx.x&31)==0) red[threadIdx.x>>5]=v;
    __syncthreads();
    if (threadIdx.x==0) g_det = red[0]|red[1]|red[2]|red[3];
  }
  __shared__ float sw[128][36];
  int b=blockIdx.x; int ch=b&31, nb=(b>>5)&31, e=b>>10;
  int r=threadIdx.x;                     // 0..127: 64 h rows then 64 gate rows
  int srow = (r<64)? (nb*64+r) : (2048 + nb*64 + (r-64));
  const float4* src = (const float4*)(W1 + ((size_t)e*4096 + srow)*DM + ch*32);
  #pragma unroll
  for (int q4=0;q4<8;q4++)
    *(float4*)(&sw[r][q4*4]) = src[q4];
  __syncthreads();
  unsigned* dst = g_W1p + ((size_t)((e*32+nb)*32 + ch))*2048;
  #pragma unroll
  for (int v=0;v<16;v++){
    int u=v*128+threadIdx.x;
    int nw=u>>10, s=(u>>9)&1, qb=(u>>7)&3, l=(u>>2)&31, el=u&3;
    int j=2*qb+(el>>1);
    int n=nw*64+j*8+(l>>2);
    int k=s*16+2*(l&3)+8*(el&1);
    dst[u] = h2(sw[n][k], sw[n][k+1]);
  }
}
// grid 4096 = [e(3)][nb(3)][ch(6)]
__global__ void k_wconv2(const float* __restrict__ W2){
  __shared__ float sw[128][36];
  int b=blockIdx.x; int ch=b&63, nb=(b>>6)&7, e=b>>9;
  int r=threadIdx.x;
  int srow = nb*128 + r;
  const float4* src = (const float4*)(W2 + ((size_t)e*1024 + srow)*DFF + ch*32);
  #pragma unroll
  for (int q4=0;q4<8;q4++)
    *(float4*)(&sw[r][q4*4]) = src[q4];
  __syncthreads();
  unsigned* dst = g_W2p + ((size_t)((e*8+nb)*64 + ch))*2048;
  #pragma unroll
  for (int v=0;v<16;v++){
    int u=v*128+threadIdx.x;
    int nw=u>>10, s=(u>>9)&1, qb=(u>>7)&3, l=(u>>2)&31, el=u&3;
    int j=2*qb+(el>>1);
    int n=nw*64+j*8+(l>>2);
    int k=s*16+2*(l&3)+8*(el&1);
    dst[u] = h2(sw[n][k], sw[n][k+1]);
  }
}

// ---------------- perm ----------------
__global__ void k_perm(const void* __restrict__ ind, const int* __restrict__ counts){
  int tb[9]; tb[0]=0;
  #pragma unroll
  for (int e=0;e<8;e++) tb[e+1] = tb[e] + ((counts[e]+127)>>7);
  if (blockIdx.x==0 && threadIdx.x<9) g_tb[threadIdx.x] = tb[threadIdx.x];
  int p = blockIdx.x*blockDim.x + threadIdx.x;
  if (p>=NROWS) return;
  int e;
  if (g_det==0u) e = (int)((const long long*)ind)[p];
  else           e = ((const int*)ind)[p];
  e &= 7;
  int s = (tb[e]<<7) + atomicAdd(&g_cnt[e],1);
  if (s >= PADROWS) s = PADROWS-1;
  g_perm[s] = p;
}

// ---------------- packA: gather + fp16 fragment-pack ----------------
__global__ void __launch_bounds__(256,1) k_packA(const float* __restrict__ x){
  __shared__ int sp[128];
  extern __shared__ float sm[];   // [128][132]
  int t = blockIdx.x>>3, kb8 = blockIdx.x&7;
  if (t>=g_tb[8]) return;
  int tid=threadIdx.x;
  if (tid<128) sp[tid]=g_perm[t*128+tid];
  __syncthreads();
  #pragma unroll
  for (int v=0;v<16;v++){
    int i=v*256+tid, row=i>>5, c4=i&31;
    int p=sp[row];
    float4 fv=make_float4(0.f,0.f,0.f,0.f);
    if (p>=0) fv = *(const float4*)(x + (size_t)(p>>1)*DM + kb8*128 + c4*4);
    *(float4*)(sm + row*132 + c4*4) = fv;
  }
  __syncthreads();
  unsigned* dst = g_Xp + (size_t)t*65536 + (size_t)kb8*8192;
  #pragma unroll
  for (int v=0;v<32;v++){
    int o=v*256+tid;                    // 0..8191 covering 4 chunks
    int cl=o>>11, u=o&2047;
    int s=u>>10, g=(u>>7)&7, l=(u>>2)&31, el=u&3;
    int row = 16*g + (l>>2) + 8*(el&1);
    int k   = cl*32 + s*16 + 2*(l&3) + 8*(el>>1);   // local col within this 128-slice
    dst[o] = h2(sm[row*132+k], sm[row*132+k+1]);
  }
}

// ---------------- GEMM: 128x128 CTA, 256 thr (4m x 2n warps, 32x64/warp),
// ---------------- K32 chunks (2 phases of k16 fp16 mma), 4-stage, 2 CTAs/SM ----------------
template<bool IS1>
__global__ void __launch_bounds__(256,2) k_gemm(float* __restrict__ out){
  constexpr int NKB = IS1 ? 32 : 64;     // K32 chunks
  extern __shared__ char smc[];
  uint32_t* smu = (uint32_t*)smc;
  float* smf = (float*)smc;
  int tid=threadIdx.x, lane=tid&31, wid=tid>>5;
  int mw=wid&3, nw=wid>>2;               // 4 m-warps x 2 n-warps
  int t, nb;
  if (IS1){ t=blockIdx.x>>5; nb=blockIdx.x&31; }
  else    { t=blockIdx.x>>3; nb=blockIdx.x&7;  }
  if (t>=g_tb[8]) return;
  int e=0;
  #pragma unroll
  for (int q=1;q<8;q++) if (t>=g_tb[q]) e=q;

  const unsigned* Ab = IS1 ? (g_Xp + (size_t)t*65536) : (g_ACT + (size_t)t*131072);
  const unsigned* B0 = IS1 ? (g_W1p + (size_t)(e*32+nb)*(32*2048))
                           : (g_W2p + (size_t)(e*8+nb)*(64*2048));

  uint32_t sb = su32(smc);
  uint32_t Asb = sb, Bsb = sb + 32768;   // A: 4 stages x 2048 u32, B: 4 x 2048 u32

  float acc[2][8][4];
  #pragma unroll
  for (int i=0;i<2;i++)
    #pragma unroll
    for (int j=0;j<8;j++)
      #pragma unroll
      for (int c=0;c<4;c++) acc[i][j][c]=0.f;

  auto load = [&](int kb,int st){
    cp16(Asb + st*8192 +        tid*16, Ab + (size_t)kb*2048 +        tid*4);
    cp16(Asb + st*8192 + 4096 + tid*16, Ab + (size_t)kb*2048 + 1024 + tid*4);
    cp16(Bsb + st*8192 +        tid*16, B0 + (size_t)kb*2048 +        tid*4);
    cp16(Bsb + st*8192 + 4096 + tid*16, B0 + (size_t)kb*2048 + 1024 + tid*4);
  };
  load(0,0); CPCOMMIT();
  load(1,1); CPCOMMIT();
  load(2,2); CPCOMMIT();

  for (int kb=0; kb<NKB; kb++){
    int st=kb&3;
    CPWAIT(2);
    __syncthreads();
    const uint32_t* A_s = smu + st*2048;
    const uint32_t* B_s = smu + 8192 + st*2048;
    #pragma unroll
    for (int s=0;s<2;s++){
      uint4 af0 = *(const uint4*)(A_s + s*1024 + (2*mw+0)*128 + lane*4);
      uint4 af1 = *(const uint4*)(A_s + s*1024 + (2*mw+1)*128 + lane*4);
      const uint32_t* bp = B_s + nw*1024 + s*512 + lane*4;
      uint4 q0=*(const uint4*)bp,       q1=*(const uint4*)(bp+128),
            q2=*(const uint4*)(bp+256), q3=*(const uint4*)(bp+384);
      if (s==0){                                   // exactly ONE commit per kb iteration
        if (kb+3<NKB) load(kb+3,(kb+3)&3);
        CPCOMMIT();
      }
      uint32_t a0[4]={af0.x,af0.y,af0.z,af0.w};
      uint32_t a1[4]={af1.x,af1.y,af1.z,af1.w};
      uint32_t qv[16]={q0.x,q0.y,q0.z,q0.w, q1.x,q1.y,q1.z,q1.w,
                       q2.x,q2.y,q2.z,q2.w, q3.x,q3.y,q3.z,q3.w};
      #pragma unroll
      for (int j=0;j<8;j++){
        uint32_t b0=qv[(j>>1)*4+(j&1)*2], b1=qv[(j>>1)*4+(j&1)*2+1];
        mma16(acc[0][j],a0,b0,b1);
        mma16(acc[1][j],a1,b0,b1);
      }
    }
  }
  CPWAIT(0);
  __syncthreads();

  if (IS1){
    // GLU: D cols 0..63 = h (nw=0), 64..127 = gate (nw=1); pair same local col.
    // ACT cols covered: nb*64..+63 -> GEMM2 K32 chunks nb*2, nb*2+1.
    float* G  = smf;                     // [64][68] gate staging
    float* Gt = smf + 64*68;             // [64][68] activation staging
    unsigned* actb = g_ACT + (size_t)t*131072;
    #pragma unroll
    for (int w=0;w<2;w++){
      if ((mw>>1)==w && nw==1){          // gate warps -> G
        #pragma unroll
        for (int mf=0;mf<2;mf++){
          int sr=(mw&1)*32+mf*16+(lane>>2);
          #pragma unroll
          for (int j=0;j<8;j++){
            int col=j*8+(lane&3)*2;
            G[sr*68+col]    =acc[mf][j][0]; G[sr*68+col+1]    =acc[mf][j][1];
            G[(sr+8)*68+col]=acc[mf][j][2]; G[(sr+8)*68+col+1]=acc[mf][j][3];
          }
        }
      }
      __syncthreads();
      if ((mw>>1)==w && nw==0){          // h warps: act = h*silu(gate) -> Gt
        #pragma unroll
        for (int mf=0;mf<2;mf++){
          int sr=(mw&1)*32+mf*16+(lane>>2);
          #pragma unroll
          for (int j=0;j<8;j++){
            int col=j*8+(lane&3)*2;
            float g0=G[sr*68+col],     g1=G[sr*68+col+1];
            float g2=G[(sr+8)*68+col], g3=G[(sr+8)*68+col+1];
            Gt[sr*68+col]      = acc[mf][j][0]*g0*(1.f/(1.f+__expf(-g0)));
            Gt[sr*68+col+1]    = acc[mf][j][1]*g1*(1.f/(1.f+__expf(-g1)));
            Gt[(sr+8)*68+col]  = acc[mf][j][2]*g2*(1.f/(1.f+__expf(-g2)));
            Gt[(sr+8)*68+col+1]= acc[mf][j][3]*g3*(1.f/(1.f+__expf(-g3)));
          }
        }
      }
      __syncthreads();
      // packed fp16 ACT write for this 64-row half: 2048 u32, 256 threads -> 8 each
      #pragma unroll
      for (int v=0;v<8;v++){
        int o=v*256+tid;
        int cl=o>>10, s2=(o>>9)&1, gl=(o>>7)&3, l=(o>>2)&31, el=o&3;
        int row = gl*16 + (l>>2) + 8*(el&1);           // 0..63 half-local
        int col = cl*32 + s2*16 + 2*(l&3) + 8*(el>>1); // 0..63
        uint32_t val = h2(Gt[row*68+col], Gt[row*68+col+1]);
        actb[(size_t)(nb*2+cl)*2048 + s2*1024 + (w*4+gl)*128 + l*4 + el] = val;
      }
      __syncthreads();
    }
  } else {
    // scatter epilogue (fp32 out, unchanged)
    #pragma unroll
    for (int mf=0;mf<2;mf++){
      int r=mw*32+mf*16+(lane>>2);
      int p0=g_perm[t*128+r], p1=g_perm[t*128+r+8];
      #pragma unroll
      for (int j=0;j<8;j++){
        int col=nb*128+nw*64+j*8+(lane&3)*2;
        if (p0>=0) *(float2*)(out+(size_t)p0*DM+col)=make_float2(acc[mf][j][0],acc[mf][j][1]);
        if (p1>=0) *(float2*)(out+(size_t)p1*DM+col)=make_float2(acc[mf][j][2],acc[mf][j][3]);
      }
    }
  }
}

// ---------------- host ----------------
extern "C" void kernel_launch(void* const* d_in, const int* in_sizes, int n_in,
                              void* d_out, int out_size){
  const float* x   = (const float*)d_in[0];
  const float* w1  = (const float*)d_in[1];
  const float* w2  = (const float*)d_in[2];
  const void*  ind = d_in[3];
  const int*   cnt = (const int*)d_in[4];
  float* out = (float*)d_out;
  (void)in_sizes; (void)n_in; (void)out_size;

  const int SMG = (4*2048 + 4*2048)*4;   // 65536 B per CTA (2 CTAs/SM)
  const int SMP = 128*132*4;             // 67584 B
  cudaFuncSetAttribute((const void*)k_gemm<true>,  cudaFuncAttributeMaxDynamicSharedMemorySize, SMG);
  cudaFuncSetAttribute((const void*)k_gemm<false>, cudaFuncAttributeMaxDynamicSharedMemorySize, SMG);
  cudaFuncSetAttribute((const void*)k_packA, cudaFuncAttributeMaxDynamicSharedMemorySize, SMP);

  k_wconv1<<<8192, 128>>>(w1, (const unsigned*)ind);  // + perm/cnt init + dtype detect
  k_perm<<<128, 256>>>(ind, cnt);                     // + publishes g_tb
  k_packA<<<MAXT*8, 256, SMP>>>(x);
  k_gemm<true ><<<MAXT*32, 256, SMG>>>(nullptr);      // 4th launch -> ncu capture slot
  k_wconv2<<<4096, 128>>>(w2);
  k_gemm<false><<<MAXT*8,  256, SMG>>>(out);
}